// round 8
// baseline (speedup 1.0000x reference)
#include <cuda_runtime.h>
#include <cuda_bf16.h>

// Problem constants
#define BB   2048
#define NN   128
#define DD   32
#define HH   8
#define NDD  4096   // N*D
#define UU   512    // per-head units
#define SCALE 0.17677669529663687f   // 1/sqrt(32)

// ---------------------------------------------------------------------------
// Scratch (static __device__ globals: allocation-free, graph-safe)
// ---------------------------------------------------------------------------
__device__ float g_Q [(size_t)HH * BB * UU];        // 33.5 MB
__device__ float g_K [(size_t)HH * BB * UU];
__device__ float g_V [(size_t)HH * BB * UU];
__device__ float g_S [(size_t)HH * BB * BB];        // 134 MB
__device__ float g_AV[(size_t)HH * BB * UU];

// ---------------------------------------------------------------------------
// GEMM (NN): C[z] = A[z] (MxK, lda=K) * B[z] (KxN, ldb=N), C row-major ldc=N
// Tiles: 128x128x16, 256 threads, 8x8 per thread. All dims divide tiles.
// ---------------------------------------------------------------------------
__global__ __launch_bounds__(256, 2)
void gemm_nn(const float* __restrict__ A, const float* __restrict__ B,
             float* __restrict__ C, int M, int N, int K,
             long sA, long sB, long sC)
{
    A += (long)blockIdx.z * sA;
    B += (long)blockIdx.z * sB;
    C += (long)blockIdx.z * sC;

    __shared__ float As[16][128];   // [k][m]
    __shared__ float Bs[16][128];   // [k][n]

    const int tid  = threadIdx.x;
    const int row0 = blockIdx.y * 128;
    const int col0 = blockIdx.x * 128;

    // A tile loads: 128 rows x 16 cols = 512 float4, 2 per thread
    const int a_r = tid >> 2;            // 0..63 (+64)
    const int a_c = (tid & 3) * 4;       // 0,4,8,12
    // B tile loads: 16 rows x 128 cols = 512 float4, 2 per thread
    const int b_r = tid >> 5;            // 0..7 (+8)
    const int b_c = (tid & 31) * 4;      // 0..124

    const int tx = tid & 15;             // col group
    const int ty = tid >> 4;             // row group

    float acc[8][8];
    #pragma unroll
    for (int i = 0; i < 8; i++)
        #pragma unroll
        for (int j = 0; j < 8; j++) acc[i][j] = 0.f;

    for (int k0 = 0; k0 < K; k0 += 16) {
        #pragma unroll
        for (int l = 0; l < 2; l++) {
            int r = a_r + l * 64;
            float4 v = *(const float4*)&A[(long)(row0 + r) * K + k0 + a_c];
            As[a_c + 0][r] = v.x; As[a_c + 1][r] = v.y;
            As[a_c + 2][r] = v.z; As[a_c + 3][r] = v.w;
        }
        #pragma unroll
        for (int l = 0; l < 2; l++) {
            int r = b_r + l * 8;
            *(float4*)&Bs[r][b_c] = *(const float4*)&B[(long)(k0 + r) * N + col0 + b_c];
        }
        __syncthreads();

        #pragma unroll
        for (int kk = 0; kk < 16; kk++) {
            float af[8], bf[8];
            #pragma unroll
            for (int i = 0; i < 8; i++) af[i] = As[kk][ty * 8 + i];
            #pragma unroll
            for (int j = 0; j < 8; j++) bf[j] = Bs[kk][tx * 8 + j];
            #pragma unroll
            for (int i = 0; i < 8; i++)
                #pragma unroll
                for (int j = 0; j < 8; j++)
                    acc[i][j] = fmaf(af[i], bf[j], acc[i][j]);
        }
        __syncthreads();
    }

    #pragma unroll
    for (int i = 0; i < 8; i++) {
        long off = (long)(row0 + ty * 8 + i) * N + col0 + tx * 8;
        float4 v0 = make_float4(acc[i][0], acc[i][1], acc[i][2], acc[i][3]);
        float4 v1 = make_float4(acc[i][4], acc[i][5], acc[i][6], acc[i][7]);
        *(float4*)&C[off]     = v0;
        *(float4*)&C[off + 4] = v1;
    }
}

// ---------------------------------------------------------------------------
// GEMM (NT): C[z] = alpha * A[z] (MxK, lda=K) * B[z]^T (B is NxK, ldb=K)
// Same tiling; both operand tiles loaded A-style (k contiguous).
// ---------------------------------------------------------------------------
__global__ __launch_bounds__(256, 2)
void gemm_nt(const float* __restrict__ A, const float* __restrict__ B,
             float* __restrict__ C, int M, int N, int K, float alpha,
             long sA, long sB, long sC)
{
    A += (long)blockIdx.z * sA;
    B += (long)blockIdx.z * sB;
    C += (long)blockIdx.z * sC;

    __shared__ float As[16][128];   // [k][m]
    __shared__ float Bs[16][128];   // [k][n]

    const int tid  = threadIdx.x;
    const int row0 = blockIdx.y * 128;
    const int col0 = blockIdx.x * 128;

    const int a_r = tid >> 2;
    const int a_c = (tid & 3) * 4;

    const int tx = tid & 15;
    const int ty = tid >> 4;

    float acc[8][8];
    #pragma unroll
    for (int i = 0; i < 8; i++)
        #pragma unroll
        for (int j = 0; j < 8; j++) acc[i][j] = 0.f;

    for (int k0 = 0; k0 < K; k0 += 16) {
        #pragma unroll
        for (int l = 0; l < 2; l++) {
            int r = a_r + l * 64;
            float4 v = *(const float4*)&A[(long)(row0 + r) * K + k0 + a_c];
            As[a_c + 0][r] = v.x; As[a_c + 1][r] = v.y;
            As[a_c + 2][r] = v.z; As[a_c + 3][r] = v.w;
        }
        #pragma unroll
        for (int l = 0; l < 2; l++) {
            int r = a_r + l * 64;   // here r indexes the N dim of B
            float4 v = *(const float4*)&B[(long)(col0 + r) * K + k0 + a_c];
            Bs[a_c + 0][r] = v.x; Bs[a_c + 1][r] = v.y;
            Bs[a_c + 2][r] = v.z; Bs[a_c + 3][r] = v.w;
        }
        __syncthreads();

        #pragma unroll
        for (int kk = 0; kk < 16; kk++) {
            float af[8], bf[8];
            #pragma unroll
            for (int i = 0; i < 8; i++) af[i] = As[kk][ty * 8 + i];
            #pragma unroll
            for (int j = 0; j < 8; j++) bf[j] = Bs[kk][tx * 8 + j];
            #pragma unroll
            for (int i = 0; i < 8; i++)
                #pragma unroll
                for (int j = 0; j < 8; j++)
                    acc[i][j] = fmaf(af[i], bf[j], acc[i][j]);
        }
        __syncthreads();
    }

    #pragma unroll
    for (int i = 0; i < 8; i++) {
        long off = (long)(row0 + ty * 8 + i) * N + col0 + tx * 8;
        float4 v0 = make_float4(acc[i][0] * alpha, acc[i][1] * alpha,
                                acc[i][2] * alpha, acc[i][3] * alpha);
        float4 v1 = make_float4(acc[i][4] * alpha, acc[i][5] * alpha,
                                acc[i][6] * alpha, acc[i][7] * alpha);
        *(float4*)&C[off]     = v0;
        *(float4*)&C[off + 4] = v1;
    }
}

// ---------------------------------------------------------------------------
// Row softmax in place: one 256-thread block per row of length 2048.
// ---------------------------------------------------------------------------
__global__ __launch_bounds__(256)
void softmax_rows(float* __restrict__ S)
{
    const int cols = BB;
    float* row = S + (long)blockIdx.x * cols;
    const int tid = threadIdx.x;
    __shared__ float sred[8];

    // max
    float m = -1e30f;
    for (int i = tid; i < cols; i += 256) m = fmaxf(m, row[i]);
    #pragma unroll
    for (int o = 16; o; o >>= 1) m = fmaxf(m, __shfl_xor_sync(0xffffffffu, m, o));
    if ((tid & 31) == 0) sred[tid >> 5] = m;
    __syncthreads();
    if (tid == 0) {
        float t = sred[0];
        #pragma unroll
        for (int i = 1; i < 8; i++) t = fmaxf(t, sred[i]);
        sred[0] = t;
    }
    __syncthreads();
    m = sred[0];
    __syncthreads();

    // exp + sum
    float s = 0.f;
    for (int i = tid; i < cols; i += 256) {
        float e = __expf(row[i] - m);
        row[i] = e;
        s += e;
    }
    #pragma unroll
    for (int o = 16; o; o >>= 1) s += __shfl_xor_sync(0xffffffffu, s, o);
    if ((tid & 31) == 0) sred[tid >> 5] = s;
    __syncthreads();
    if (tid == 0) {
        float t = 0.f;
        #pragma unroll
        for (int i = 0; i < 8; i++) t += sred[i];
        sred[0] = t;
    }
    __syncthreads();
    const float inv = 1.f / sred[0];

    for (int i = tid; i < cols; i += 256) row[i] *= inv;
}

// ---------------------------------------------------------------------------
// Epilogue: head-concat reorder fused with out = concat @ Wo (32x32).
// One warp per (b, n) row; lane l holds concat[b,n,l]; shuffle-broadcast GEMV.
//   concat[b,n,d'] = AV[h=d'/4][b][n*4 + d'%4]
// ---------------------------------------------------------------------------
__global__ __launch_bounds__(256)
void out_proj(const float* __restrict__ AV, const float* __restrict__ Wo,
              float* __restrict__ out)
{
    __shared__ float Wos[32 * 32];
    const int tid = threadIdx.x;
    for (int i = tid; i < 1024; i += 256) Wos[i] = Wo[i];
    __syncthreads();

    const int warp = tid >> 5, lane = tid & 31;
    const int nwarps = (256 >> 5) * gridDim.x;
    const long nrows = (long)BB * NN;   // 262144

    for (long r = (long)blockIdx.x * 8 + warp; r < nrows; r += nwarps) {
        const int b = (int)(r >> 7);
        const int n = (int)(r & 127);
        const int h = lane >> 2, j = lane & 3;
        const float c = AV[((long)h * BB + b) * UU + n * 4 + j];

        float acc = 0.f;
        #pragma unroll
        for (int d = 0; d < 32; d++) {
            float v = __shfl_sync(0xffffffffu, c, d);
            acc = fmaf(v, Wos[d * 32 + lane], acc);
        }
        out[r * DD + lane] = acc;
    }
}

// ---------------------------------------------------------------------------
// Launch
// ---------------------------------------------------------------------------
extern "C" void kernel_launch(void* const* d_in, const int* in_sizes, int n_in,
                              void* d_out, int out_size)
{
    const float* x  = (const float*)d_in[0];   // (2048,128,32) = (2048,4096)
    const float* Wq = (const float*)d_in[1];   // (8,4096,512)
    const float* Wk = (const float*)d_in[2];
    const float* Wv = (const float*)d_in[3];
    const float* Wo = (const float*)d_in[4];   // (32,32)
    float* out = (float*)d_out;

    float *Q, *K, *V, *S, *AV;
    cudaGetSymbolAddress((void**)&Q,  g_Q);
    cudaGetSymbolAddress((void**)&K,  g_K);
    cudaGetSymbolAddress((void**)&V,  g_V);
    cudaGetSymbolAddress((void**)&S,  g_S);
    cudaGetSymbolAddress((void**)&AV, g_AV);

    const long sW  = (long)NDD * UU;     // per-head weight stride
    const long sQ  = (long)BB * UU;      // per-head Q/K/V/AV stride
    const long sS  = (long)BB * BB;      // per-head scores stride

    dim3 blk(256);

    // 1-3. Projections: Q/K/V[h] = xf @ W[h]   (M=2048, N=512, K=4096, 8 heads)
    dim3 gproj(UU / 128, BB / 128, HH);                 // (4,16,8)
    gemm_nn<<<gproj, blk>>>(x, Wq, Q, BB, UU, NDD, 0L, sW, sQ);
    gemm_nn<<<gproj, blk>>>(x, Wk, K, BB, UU, NDD, 0L, sW, sQ);
    gemm_nn<<<gproj, blk>>>(x, Wv, V, BB, UU, NDD, 0L, sW, sQ);

    // 4. S[h] = scale * Q[h] @ K[h]^T          (M=N=2048, K=512)
    dim3 gsc(BB / 128, BB / 128, HH);                   // (16,16,8)
    gemm_nt<<<gsc, blk>>>(Q, K, S, BB, BB, UU, SCALE, sQ, sQ, sS);

    // 5. softmax over last dim of S            (8*2048 rows of 2048)
    softmax_rows<<<HH * BB, 256>>>(S);

    // 6. AV[h] = S[h] @ V[h]                   (M=2048, N=512, K=2048)
    dim3 gav(UU / 128, BB / 128, HH);                   // (4,16,8)
    gemm_nn<<<gav, blk>>>(S, V, AV, BB, UU, BB, sS, sQ, sQ);

    // 7. reorder + output projection
    out_proj<<<2048, 256>>>(AV, Wo, out);
}

// round 9
// speedup vs baseline: 1.4294x; 1.4294x over previous
#include <cuda_runtime.h>
#include <cuda_bf16.h>
#include <cstdint>

// Problem constants
#define BB   2048
#define NN   128
#define DD   32
#define HH   8
#define NDD  4096   // N*D
#define UU   512    // per-head units
#define SCALE 0.17677669529663687f   // 1/sqrt(32)

// ---------------------------------------------------------------------------
// Scratch (static __device__ globals: allocation-free, graph-safe)
// ---------------------------------------------------------------------------
__device__ __nv_bfloat16 g_Xh[(size_t)BB * NDD];
__device__ __nv_bfloat16 g_Xl[(size_t)BB * NDD];
__device__ __nv_bfloat16 g_Wqh[(size_t)HH * UU * NDD];   // transposed: [h][u][nd]
__device__ __nv_bfloat16 g_Wql[(size_t)HH * UU * NDD];
__device__ __nv_bfloat16 g_Wkh[(size_t)HH * UU * NDD];
__device__ __nv_bfloat16 g_Wkl[(size_t)HH * UU * NDD];
__device__ __nv_bfloat16 g_Wvh[(size_t)HH * UU * NDD];
__device__ __nv_bfloat16 g_Wvl[(size_t)HH * UU * NDD];
__device__ float g_Q [(size_t)HH * BB * UU];
__device__ float g_K [(size_t)HH * BB * UU];
__device__ float g_V [(size_t)HH * BB * UU];
__device__ __nv_bfloat16 g_Qh[(size_t)HH * BB * UU];
__device__ __nv_bfloat16 g_Ql[(size_t)HH * BB * UU];
__device__ __nv_bfloat16 g_Kh[(size_t)HH * BB * UU];
__device__ __nv_bfloat16 g_Kl[(size_t)HH * BB * UU];
__device__ __nv_bfloat16 g_Vth[(size_t)HH * UU * BB];    // transposed: [h][u][b]
__device__ __nv_bfloat16 g_Vtl[(size_t)HH * UU * BB];
__device__ float g_S [(size_t)HH * BB * BB];
__device__ __nv_bfloat16 g_Sh[(size_t)HH * BB * BB];
__device__ __nv_bfloat16 g_Sl[(size_t)HH * BB * BB];
__device__ float g_AV[(size_t)HH * BB * UU];

// ---------------------------------------------------------------------------
// PTX helpers
// ---------------------------------------------------------------------------
__device__ __forceinline__ uint32_t cvta_smem(const void* p) {
    uint32_t a;
    asm("{ .reg .u64 t; cvta.to.shared.u64 t, %1; cvt.u32.u64 %0, t; }" : "=r"(a) : "l"(p));
    return a;
}
__device__ __forceinline__ uint32_t lds_b32(uint32_t a) {
    uint32_t v; asm volatile("ld.shared.b32 %0, [%1];" : "=r"(v) : "r"(a)); return v;
}
#define CPA16(dst, src) asm volatile("cp.async.cg.shared.global [%0], [%1], 16;" :: "r"(dst), "l"(src))
#define CPC()  asm volatile("cp.async.commit_group;")
#define CPW0() asm volatile("cp.async.wait_group 0;")
#define MMA_BF16(d, a, b) asm volatile( \
  "mma.sync.aligned.m16n8k16.row.col.f32.bf16.bf16.f32 " \
  "{%0,%1,%2,%3},{%4,%5,%6,%7},{%8,%9},{%0,%1,%2,%3};" \
  : "+f"((d)[0]), "+f"((d)[1]), "+f"((d)[2]), "+f"((d)[3]) \
  : "r"((a)[0]), "r"((a)[1]), "r"((a)[2]), "r"((a)[3]), "r"((b)[0]), "r"((b)[1]))

// ---------------------------------------------------------------------------
// Split-bf16 3-MMA GEMM: C[z] = alpha * A[z] (Mx K, k-major) * B[z]^T
// Both operands stored [row][k] (A: m rows, B: n rows). C row-major ldc=N.
// Block tile 128x128x32, 8 warps (2x4), warp tile 64x32.
// smem: 2 stages x 4 planes (Ah,Al,Bh,Bl), each 128 rows x pitch 40 bf16.
// ---------------------------------------------------------------------------
#define SPITCH 40
#define PLANEB (128 * SPITCH * 2)   // 10240 bytes per plane
#define STAGEB (4 * PLANEB)         // 40960 bytes per stage
#define GEMM_SMEM (2 * STAGEB)      // 81920 bytes

__global__ __launch_bounds__(256)
void gemm3x(const __nv_bfloat16* __restrict__ Ah, const __nv_bfloat16* __restrict__ Al,
            const __nv_bfloat16* __restrict__ Bh, const __nv_bfloat16* __restrict__ Bl,
            float* __restrict__ C, int N, int K, float alpha,
            long sA, long sB, long sC)
{
    extern __shared__ char smem_raw[];
    const uint32_t sb = cvta_smem(smem_raw);

    Ah += (long)blockIdx.z * sA;  Al += (long)blockIdx.z * sA;
    Bh += (long)blockIdx.z * sB;  Bl += (long)blockIdx.z * sB;
    C  += (long)blockIdx.z * sC;

    const int tid  = threadIdx.x;
    const int warp = tid >> 5, lane = tid & 31;
    const int wm = warp >> 2, wn = warp & 3;        // 2 x 4 warp grid
    const int g  = lane >> 2, tg = lane & 3;        // mma lane mapping
    const int row0 = blockIdx.y * 128, col0 = blockIdx.x * 128;

    // global->smem: 512 16B chunks per plane; thread handles rows r0, r0+64
    const int r0  = tid >> 2;
    const int k8a = (tid & 3) * 8;

    float acc[4][4][4];
    #pragma unroll
    for (int i = 0; i < 4; i++)
        #pragma unroll
        for (int j = 0; j < 4; j++)
            #pragma unroll
            for (int q = 0; q < 4; q++) acc[i][j][q] = 0.f;

    auto issue = [&](int s, int k0) {
        uint32_t st = sb + (uint32_t)s * STAGEB;
        uint32_t d0 = st + (uint32_t)(r0 * SPITCH + k8a) * 2;
        uint32_t d1 = st + (uint32_t)((r0 + 64) * SPITCH + k8a) * 2;
        const long oA0 = (long)(row0 + r0)      * K + k0 + k8a;
        const long oA1 = (long)(row0 + r0 + 64) * K + k0 + k8a;
        const long oB0 = (long)(col0 + r0)      * K + k0 + k8a;
        const long oB1 = (long)(col0 + r0 + 64) * K + k0 + k8a;
        CPA16(d0,              Ah + oA0);  CPA16(d1,              Ah + oA1);
        CPA16(d0 + PLANEB,     Al + oA0);  CPA16(d1 + PLANEB,     Al + oA1);
        CPA16(d0 + 2*PLANEB,   Bh + oB0);  CPA16(d1 + 2*PLANEB,   Bh + oB1);
        CPA16(d0 + 3*PLANEB,   Bl + oB0);  CPA16(d1 + 3*PLANEB,   Bl + oB1);
    };

    const int nk = K / 32;
    issue(0, 0); CPC();

    for (int t = 0; t < nk; t++) {
        CPW0();
        __syncthreads();
        if (t + 1 < nk) { issue((t + 1) & 1, (t + 1) * 32); CPC(); }

        const uint32_t st = sb + (uint32_t)(t & 1) * STAGEB;
        #pragma unroll
        for (int kk = 0; kk < 2; kk++) {
            uint32_t ah[4][4], al_[4][4], bh[4][2], bl_[4][2];
            #pragma unroll
            for (int mf = 0; mf < 4; mf++) {
                int r = wm * 64 + mf * 16 + g;
                uint32_t p0 = st + (uint32_t)(r * SPITCH + kk * 16 + 2 * tg) * 2;
                uint32_t p1 = p0 + 8 * SPITCH * 2;
                ah[mf][0]  = lds_b32(p0);               ah[mf][1]  = lds_b32(p1);
                ah[mf][2]  = lds_b32(p0 + 16);          ah[mf][3]  = lds_b32(p1 + 16);
                al_[mf][0] = lds_b32(p0 + PLANEB);      al_[mf][1] = lds_b32(p1 + PLANEB);
                al_[mf][2] = lds_b32(p0 + 16 + PLANEB); al_[mf][3] = lds_b32(p1 + 16 + PLANEB);
            }
            #pragma unroll
            for (int nf = 0; nf < 4; nf++) {
                int r = wn * 32 + nf * 8 + g;
                uint32_t p0 = st + 2 * PLANEB + (uint32_t)(r * SPITCH + kk * 16 + 2 * tg) * 2;
                bh[nf][0]  = lds_b32(p0);               bh[nf][1]  = lds_b32(p0 + 16);
                bl_[nf][0] = lds_b32(p0 + PLANEB);      bl_[nf][1] = lds_b32(p0 + 16 + PLANEB);
            }
            #pragma unroll
            for (int mf = 0; mf < 4; mf++)
                #pragma unroll
                for (int nf = 0; nf < 4; nf++) {
                    MMA_BF16(acc[mf][nf], ah[mf],  bh[nf]);
                    MMA_BF16(acc[mf][nf], ah[mf],  bl_[nf]);
                    MMA_BF16(acc[mf][nf], al_[mf], bh[nf]);
                }
        }
        __syncthreads();
    }

    #pragma unroll
    for (int mf = 0; mf < 4; mf++) {
        int r = row0 + wm * 64 + mf * 16 + g;
        #pragma unroll
        for (int nf = 0; nf < 4; nf++) {
            int c = col0 + wn * 32 + nf * 8 + 2 * tg;
            float2 v0 = make_float2(acc[mf][nf][0] * alpha, acc[mf][nf][1] * alpha);
            float2 v1 = make_float2(acc[mf][nf][2] * alpha, acc[mf][nf][3] * alpha);
            *(float2*)&C[(long)r * N + c]       = v0;
            *(float2*)&C[(long)(r + 8) * N + c] = v1;
        }
    }
}

// ---------------------------------------------------------------------------
// fp32 -> (bf16 hi, bf16 lo) elementwise split
// ---------------------------------------------------------------------------
__global__ __launch_bounds__(256)
void split_conv(const float* __restrict__ in, __nv_bfloat16* __restrict__ hi,
                __nv_bfloat16* __restrict__ lo, long n)
{
    long i = (long)blockIdx.x * blockDim.x + threadIdx.x;
    const long stride = (long)gridDim.x * blockDim.x;
    for (; i < n; i += stride) {
        float v = in[i];
        __nv_bfloat16 h = __float2bfloat16(v);
        hi[i] = h;
        lo[i] = __float2bfloat16(v - __bfloat162float(h));
    }
}

// ---------------------------------------------------------------------------
// fp32 [batch][R][C] -> transposed bf16 hi/lo [batch][C][R]
// ---------------------------------------------------------------------------
__global__ __launch_bounds__(256)
void split_conv_T(const float* __restrict__ in, __nv_bfloat16* __restrict__ hi,
                  __nv_bfloat16* __restrict__ lo, int R, int C)
{
    __shared__ float t[32][33];
    const long bo = (long)blockIdx.z * R * C;
    in += bo; hi += bo; lo += bo;
    const int rt = blockIdx.y * 32, ct = blockIdx.x * 32;
    #pragma unroll
    for (int j = 0; j < 4; j++)
        t[threadIdx.y + j * 8][threadIdx.x] =
            in[(long)(rt + threadIdx.y + j * 8) * C + ct + threadIdx.x];
    __syncthreads();
    #pragma unroll
    for (int j = 0; j < 4; j++) {
        float v = t[threadIdx.x][threadIdx.y + j * 8];
        long o = (long)(ct + threadIdx.y + j * 8) * R + rt + threadIdx.x;
        __nv_bfloat16 h = __float2bfloat16(v);
        hi[o] = h;
        lo[o] = __float2bfloat16(v - __bfloat162float(h));
    }
}

// ---------------------------------------------------------------------------
// Row softmax: read fp32 S (scratch, rewritten each call), write bf16 hi/lo.
// One 256-thread block per row of length 2048.
// ---------------------------------------------------------------------------
__global__ __launch_bounds__(256)
void softmax_split(float* __restrict__ S, __nv_bfloat16* __restrict__ Sh,
                   __nv_bfloat16* __restrict__ Sl)
{
    const int cols = BB;
    float* row = S + (long)blockIdx.x * cols;
    __nv_bfloat16* rh = Sh + (long)blockIdx.x * cols;
    __nv_bfloat16* rl = Sl + (long)blockIdx.x * cols;
    const int tid = threadIdx.x;
    __shared__ float sred[8];

    float m = -1e30f;
    for (int i = tid; i < cols; i += 256) m = fmaxf(m, row[i]);
    #pragma unroll
    for (int o = 16; o; o >>= 1) m = fmaxf(m, __shfl_xor_sync(0xffffffffu, m, o));
    if ((tid & 31) == 0) sred[tid >> 5] = m;
    __syncthreads();
    if (tid == 0) {
        float t = sred[0];
        #pragma unroll
        for (int i = 1; i < 8; i++) t = fmaxf(t, sred[i]);
        sred[0] = t;
    }
    __syncthreads();
    m = sred[0];
    __syncthreads();

    float s = 0.f;
    for (int i = tid; i < cols; i += 256) {
        float e = __expf(row[i] - m);
        row[i] = e;
        s += e;
    }
    #pragma unroll
    for (int o = 16; o; o >>= 1) s += __shfl_xor_sync(0xffffffffu, s, o);
    if ((tid & 31) == 0) sred[tid >> 5] = s;
    __syncthreads();
    if (tid == 0) {
        float t = 0.f;
        #pragma unroll
        for (int i = 0; i < 8; i++) t += sred[i];
        sred[0] = t;
    }
    __syncthreads();
    const float inv = 1.f / sred[0];

    for (int i = tid; i < cols; i += 256) {
        float p = row[i] * inv;
        __nv_bfloat16 h = __float2bfloat16(p);
        rh[i] = h;
        rl[i] = __float2bfloat16(p - __bfloat162float(h));
    }
}

// ---------------------------------------------------------------------------
// Epilogue: head-concat reorder fused with out = concat @ Wo (32x32).
// ---------------------------------------------------------------------------
__global__ __launch_bounds__(256)
void out_proj(const float* __restrict__ AV, const float* __restrict__ Wo,
              float* __restrict__ out)
{
    __shared__ float Wos[32 * 32];
    const int tid = threadIdx.x;
    for (int i = tid; i < 1024; i += 256) Wos[i] = Wo[i];
    __syncthreads();

    const int warp = tid >> 5, lane = tid & 31;
    const int nwarps = (256 >> 5) * gridDim.x;
    const long nrows = (long)BB * NN;

    for (long r = (long)blockIdx.x * 8 + warp; r < nrows; r += nwarps) {
        const int b = (int)(r >> 7);
        const int n = (int)(r & 127);
        const int h = lane >> 2, j = lane & 3;
        const float c = AV[((long)h * BB + b) * UU + n * 4 + j];

        float acc = 0.f;
        #pragma unroll
        for (int d = 0; d < 32; d++) {
            float v = __shfl_sync(0xffffffffu, c, d);
            acc = fmaf(v, Wos[d * 32 + lane], acc);
        }
        out[r * DD + lane] = acc;
    }
}

// ---------------------------------------------------------------------------
// Launch
// ---------------------------------------------------------------------------
extern "C" void kernel_launch(void* const* d_in, const int* in_sizes, int n_in,
                              void* d_out, int out_size)
{
    const float* x  = (const float*)d_in[0];   // (2048,128,32) -> (2048,4096)
    const float* Wq = (const float*)d_in[1];   // (8,4096,512)
    const float* Wk = (const float*)d_in[2];
    const float* Wv = (const float*)d_in[3];
    const float* Wo = (const float*)d_in[4];   // (32,32)
    float* out = (float*)d_out;

    static int smem_set = 0;
    cudaFuncSetAttribute(gemm3x, cudaFuncAttributeMaxDynamicSharedMemorySize, GEMM_SMEM);
    (void)smem_set;

    __nv_bfloat16 *Xh, *Xl, *Wqh, *Wql, *Wkh, *Wkl, *Wvh, *Wvl;
    __nv_bfloat16 *Qh, *Ql, *Kh, *Kl, *Vth, *Vtl, *Sh, *Sl;
    float *Q, *K, *V, *S, *AV;
    cudaGetSymbolAddress((void**)&Xh,  g_Xh);  cudaGetSymbolAddress((void**)&Xl,  g_Xl);
    cudaGetSymbolAddress((void**)&Wqh, g_Wqh); cudaGetSymbolAddress((void**)&Wql, g_Wql);
    cudaGetSymbolAddress((void**)&Wkh, g_Wkh); cudaGetSymbolAddress((void**)&Wkl, g_Wkl);
    cudaGetSymbolAddress((void**)&Wvh, g_Wvh); cudaGetSymbolAddress((void**)&Wvl, g_Wvl);
    cudaGetSymbolAddress((void**)&Q,   g_Q);   cudaGetSymbolAddress((void**)&K,   g_K);
    cudaGetSymbolAddress((void**)&V,   g_V);
    cudaGetSymbolAddress((void**)&Qh,  g_Qh);  cudaGetSymbolAddress((void**)&Ql,  g_Ql);
    cudaGetSymbolAddress((void**)&Kh,  g_Kh);  cudaGetSymbolAddress((void**)&Kl,  g_Kl);
    cudaGetSymbolAddress((void**)&Vth, g_Vth); cudaGetSymbolAddress((void**)&Vtl, g_Vtl);
    cudaGetSymbolAddress((void**)&S,   g_S);
    cudaGetSymbolAddress((void**)&Sh,  g_Sh);  cudaGetSymbolAddress((void**)&Sl,  g_Sl);
    cudaGetSymbolAddress((void**)&AV,  g_AV);

    const long sWt = (long)UU * NDD;     // per-head transposed-weight stride
    const long sQ  = (long)BB * UU;      // per-head Q/K/V/AV stride
    const long sVt = (long)UU * BB;      // per-head V^T stride
    const long sS  = (long)BB * BB;      // per-head scores stride

    dim3 blk(256);
    dim3 tblk(32, 8);

    // 0. split-convert inputs
    split_conv<<<4096, blk>>>(x, Xh, Xl, (long)BB * NDD);
    dim3 gWT(UU / 32, NDD / 32, HH);                    // (16,128,8)
    split_conv_T<<<gWT, tblk>>>(Wq, Wqh, Wql, NDD, UU);
    split_conv_T<<<gWT, tblk>>>(Wk, Wkh, Wkl, NDD, UU);
    split_conv_T<<<gWT, tblk>>>(Wv, Wvh, Wvl, NDD, UU);

    // 1-3. Projections: Q/K/V[h] = X @ W[h]   (M=2048, N=512, K=4096)
    dim3 gproj(UU / 128, BB / 128, HH);                 // (4,16,8)
    gemm3x<<<gproj, blk, GEMM_SMEM>>>(Xh, Xl, Wqh, Wql, Q, UU, NDD, 1.f, 0L, sWt, sQ);
    gemm3x<<<gproj, blk, GEMM_SMEM>>>(Xh, Xl, Wkh, Wkl, K, UU, NDD, 1.f, 0L, sWt, sQ);
    gemm3x<<<gproj, blk, GEMM_SMEM>>>(Xh, Xl, Wvh, Wvl, V, UU, NDD, 1.f, 0L, sWt, sQ);

    // 4. split-convert Q, K; transpose-split V
    split_conv<<<4096, blk>>>(Q, Qh, Ql, (long)HH * BB * UU);
    split_conv<<<4096, blk>>>(K, Kh, Kl, (long)HH * BB * UU);
    dim3 gVT(UU / 32, BB / 32, HH);                     // (16,64,8)
    split_conv_T<<<gVT, tblk>>>(V, Vth, Vtl, BB, UU);

    // 5. S[h] = scale * Q[h] @ K[h]^T          (M=N=2048, K=512) — K already k-major
    dim3 gsc(BB / 128, BB / 128, HH);                   // (16,16,8)
    gemm3x<<<gsc, blk, GEMM_SMEM>>>(Qh, Ql, Kh, Kl, S, BB, UU, SCALE, sQ, sQ, sS);

    // 6. softmax rows -> bf16 hi/lo planes
    softmax_split<<<HH * BB, blk>>>(S, Sh, Sl);

    // 7. AV[h] = P[h] @ V[h]                   (M=2048, N=512, K=2048)
    dim3 gav(UU / 128, BB / 128, HH);                   // (4,16,8)
    gemm3x<<<gav, blk, GEMM_SMEM>>>(Sh, Sl, Vth, Vtl, AV, UU, BB, 1.f, sS, sVt, sQ);

    // 8. reorder + output projection
    out_proj<<<2048, blk>>>(AV, Wo, out);
}

// round 11
// speedup vs baseline: 2.2438x; 1.5698x over previous
#include <cuda_runtime.h>
#include <cuda_bf16.h>
#include <cstdint>

// Problem constants
#define BB   2048
#define NN   128
#define DD   32
#define HH   8
#define NDD  4096   // N*D
#define UU   512    // per-head units
#define SCALE 0.17677669529663687f   // 1/sqrt(32)

// ---------------------------------------------------------------------------
// Scratch (static __device__ globals: allocation-free, graph-safe)
// ---------------------------------------------------------------------------
__device__ __nv_bfloat16 g_Xh[(size_t)BB * NDD];
__device__ __nv_bfloat16 g_Xl[(size_t)BB * NDD];
__device__ __nv_bfloat16 g_Wqh[(size_t)HH * UU * NDD];   // transposed: [h][u][nd]
__device__ __nv_bfloat16 g_Wql[(size_t)HH * UU * NDD];
__device__ __nv_bfloat16 g_Wkh[(size_t)HH * UU * NDD];
__device__ __nv_bfloat16 g_Wkl[(size_t)HH * UU * NDD];
__device__ __nv_bfloat16 g_Wvh[(size_t)HH * UU * NDD];
__device__ __nv_bfloat16 g_Wvl[(size_t)HH * UU * NDD];
__device__ float g_V [(size_t)HH * BB * UU];
__device__ __nv_bfloat16 g_Qh[(size_t)HH * BB * UU];
__device__ __nv_bfloat16 g_Ql[(size_t)HH * BB * UU];
__device__ __nv_bfloat16 g_Kh[(size_t)HH * BB * UU];
__device__ __nv_bfloat16 g_Kl[(size_t)HH * BB * UU];
__device__ __nv_bfloat16 g_Vth[(size_t)HH * UU * BB];    // transposed: [h][u][b]
__device__ __nv_bfloat16 g_Vtl[(size_t)HH * UU * BB];
__device__ float g_S [(size_t)HH * BB * BB];
__device__ __nv_bfloat16 g_Sh[(size_t)HH * BB * BB];
__device__ __nv_bfloat16 g_Sl[(size_t)HH * BB * BB];
__device__ float g_AV[(size_t)HH * BB * UU];

// ---------------------------------------------------------------------------
// PTX helpers
// ---------------------------------------------------------------------------
__device__ __forceinline__ uint32_t cvta_smem(const void* p) {
    uint32_t a;
    asm("{ .reg .u64 t; cvta.to.shared.u64 t, %1; cvt.u32.u64 %0, t; }" : "=r"(a) : "l"(p));
    return a;
}
#define CPA16(dst, src) asm volatile("cp.async.cg.shared.global [%0], [%1], 16;" :: "r"(dst), "l"(src))
#define CPC()  asm volatile("cp.async.commit_group;")
#define CPW0() asm volatile("cp.async.wait_group 0;")
#define MMA_BF16(d, a, b) asm volatile( \
  "mma.sync.aligned.m16n8k16.row.col.f32.bf16.bf16.f32 " \
  "{%0,%1,%2,%3},{%4,%5,%6,%7},{%8,%9},{%0,%1,%2,%3};" \
  : "+f"((d)[0]), "+f"((d)[1]), "+f"((d)[2]), "+f"((d)[3]) \
  : "r"((a)[0]), "r"((a)[1]), "r"((a)[2]), "r"((a)[3]), "r"((b)[0]), "r"((b)[1]))

__device__ __forceinline__ void ldsm4(uint32_t* r, uint32_t addr) {
    asm volatile("ldmatrix.sync.aligned.m8n8.x4.shared.b16 {%0,%1,%2,%3}, [%4];"
        : "=r"(r[0]), "=r"(r[1]), "=r"(r[2]), "=r"(r[3]) : "r"(addr));
}

// ---------------------------------------------------------------------------
// Split-bf16 3-MMA GEMM: C[z] = alpha * A[z] (MxK, k-major) * B[z]^T
// Both operands stored [row][k] (A: m rows, B: n rows). C row-major ldc=N.
// Block tile 128x128x32, 8 warps (2x4), warp tile 64x32, ldmatrix frag loads.
// smem: 2 stages x 4 planes (Ah,Al,Bh,Bl), each 128 rows x pitch 40 bf16.
// MODE 0: write fp32 Cf.  MODE 1: write bf16 hi/lo split (Ch, Cl).
// ---------------------------------------------------------------------------
#define SPITCH 40
#define PLANEB (128 * SPITCH * 2)   // 10240 bytes per plane
#define STAGEB (4 * PLANEB)         // 40960 bytes per stage
#define GEMM_SMEM (2 * STAGEB)      // 81920 bytes

template<int MODE>
__global__ __launch_bounds__(256, 2)
void gemm3x(const __nv_bfloat16* __restrict__ Ah, const __nv_bfloat16* __restrict__ Al,
            const __nv_bfloat16* __restrict__ Bh, const __nv_bfloat16* __restrict__ Bl,
            float* __restrict__ Cf, __nv_bfloat16* __restrict__ Ch,
            __nv_bfloat16* __restrict__ Cl,
            int N, int K, float alpha, long sA, long sB, long sC)
{
    extern __shared__ char smem_raw[];
    const uint32_t sb = cvta_smem(smem_raw);

    Ah += (long)blockIdx.z * sA;  Al += (long)blockIdx.z * sA;
    Bh += (long)blockIdx.z * sB;  Bl += (long)blockIdx.z * sB;

    const int tid  = threadIdx.x;
    const int warp = tid >> 5, lane = tid & 31;
    const int wm = warp >> 2, wn = warp & 3;        // 2 x 4 warp grid
    const int g  = lane >> 2, tg = lane & 3;        // mma lane mapping
    const int row0 = blockIdx.y * 128, col0 = blockIdx.x * 128;

    // global->smem: 512 16B chunks per plane; thread handles rows r0, r0+64
    const int r0  = tid >> 2;
    const int k8a = (tid & 3) * 8;

    // ldmatrix lane addressing: lanes 0-15 rows +0..15 @k, lanes 16-31 same rows @k+8
    const int lrow = lane & 15;
    const int lk   = (lane >> 4) * 8;

    float acc[4][4][4];
    #pragma unroll
    for (int i = 0; i < 4; i++)
        #pragma unroll
        for (int j = 0; j < 4; j++)
            #pragma unroll
            for (int q = 0; q < 4; q++) acc[i][j][q] = 0.f;

    auto issue = [&](int s, int k0) {
        uint32_t st = sb + (uint32_t)s * STAGEB;
        uint32_t d0 = st + (uint32_t)(r0 * SPITCH + k8a) * 2;
        uint32_t d1 = st + (uint32_t)((r0 + 64) * SPITCH + k8a) * 2;
        const long oA0 = (long)(row0 + r0)      * K + k0 + k8a;
        const long oA1 = (long)(row0 + r0 + 64) * K + k0 + k8a;
        const long oB0 = (long)(col0 + r0)      * K + k0 + k8a;
        const long oB1 = (long)(col0 + r0 + 64) * K + k0 + k8a;
        CPA16(d0,              Ah + oA0);  CPA16(d1,              Ah + oA1);
        CPA16(d0 + PLANEB,     Al + oA0);  CPA16(d1 + PLANEB,     Al + oA1);
        CPA16(d0 + 2*PLANEB,   Bh + oB0);  CPA16(d1 + 2*PLANEB,   Bh + oB1);
        CPA16(d0 + 3*PLANEB,   Bl + oB0);  CPA16(d1 + 3*PLANEB,   Bl + oB1);
    };

    const int nk = K / 32;
    issue(0, 0); CPC();

    for (int t = 0; t < nk; t++) {
        CPW0();
        __syncthreads();
        if (t + 1 < nk) { issue((t + 1) & 1, (t + 1) * 32); CPC(); }

        const uint32_t st = sb + (uint32_t)(t & 1) * STAGEB;
        #pragma unroll
        for (int kk = 0; kk < 2; kk++) {
            // per-warp fragment base addresses for this kk
            const uint32_t a_ad = st +
                (uint32_t)((wm * 64 + lrow) * SPITCH + kk * 16 + lk) * 2;
            const uint32_t b_ad = st + 2 * PLANEB +
                (uint32_t)((wn * 32 + lrow) * SPITCH + kk * 16 + lk) * 2;

            uint32_t ah[4][4], al_[4][4], bh[4][2], bl_[4][2];
            #pragma unroll
            for (int mf = 0; mf < 4; mf++) {
                const uint32_t off = (uint32_t)(mf * 16 * SPITCH) * 2;
                ldsm4(ah[mf],  a_ad + off);
                ldsm4(al_[mf], a_ad + off + PLANEB);
            }
            #pragma unroll
            for (int jb = 0; jb < 2; jb++) {
                const uint32_t off = (uint32_t)(jb * 16 * SPITCH) * 2;
                uint32_t th[4], tl[4];
                ldsm4(th, b_ad + off);
                ldsm4(tl, b_ad + off + PLANEB);
                bh[2*jb][0]   = th[0]; bh[2*jb+1][0] = th[1];
                bh[2*jb][1]   = th[2]; bh[2*jb+1][1] = th[3];
                bl_[2*jb][0]  = tl[0]; bl_[2*jb+1][0] = tl[1];
                bl_[2*jb][1]  = tl[2]; bl_[2*jb+1][1] = tl[3];
            }
            #pragma unroll
            for (int mf = 0; mf < 4; mf++)
                #pragma unroll
                for (int nf = 0; nf < 4; nf++) {
                    MMA_BF16(acc[mf][nf], ah[mf],  bh[nf]);
                    MMA_BF16(acc[mf][nf], ah[mf],  bl_[nf]);
                    MMA_BF16(acc[mf][nf], al_[mf], bh[nf]);
                }
        }
        __syncthreads();
    }

    if (MODE == 0) {
        float* C = Cf + (long)blockIdx.z * sC;
        #pragma unroll
        for (int mf = 0; mf < 4; mf++) {
            int r = row0 + wm * 64 + mf * 16 + g;
            #pragma unroll
            for (int nf = 0; nf < 4; nf++) {
                int c = col0 + wn * 32 + nf * 8 + 2 * tg;
                float2 v0 = make_float2(acc[mf][nf][0] * alpha, acc[mf][nf][1] * alpha);
                float2 v1 = make_float2(acc[mf][nf][2] * alpha, acc[mf][nf][3] * alpha);
                *(float2*)&C[(long)r * N + c]       = v0;
                *(float2*)&C[(long)(r + 8) * N + c] = v1;
            }
        }
    } else {
        __nv_bfloat16* CH = Ch + (long)blockIdx.z * sC;
        __nv_bfloat16* CL = Cl + (long)blockIdx.z * sC;
        #pragma unroll
        for (int mf = 0; mf < 4; mf++) {
            int r = row0 + wm * 64 + mf * 16 + g;
            #pragma unroll
            for (int nf = 0; nf < 4; nf++) {
                int c = col0 + wn * 32 + nf * 8 + 2 * tg;
                #pragma unroll
                for (int half = 0; half < 2; half++) {   // rows r, r+8
                    float vx = acc[mf][nf][2*half]     * alpha;
                    float vy = acc[mf][nf][2*half + 1] * alpha;
                    __nv_bfloat16 hx = __float2bfloat16(vx);
                    __nv_bfloat16 hy = __float2bfloat16(vy);
                    __nv_bfloat162 ph; ph.x = hx; ph.y = hy;
                    __nv_bfloat162 pl;
                    pl.x = __float2bfloat16(vx - __bfloat162float(hx));
                    pl.y = __float2bfloat16(vy - __bfloat162float(hy));
                    long o = (long)(r + 8*half) * N + c;
                    *(__nv_bfloat162*)&CH[o] = ph;
                    *(__nv_bfloat162*)&CL[o] = pl;
                }
            }
        }
    }
}

// ---------------------------------------------------------------------------
// fp32 -> (bf16 hi, bf16 lo) elementwise split
// ---------------------------------------------------------------------------
__global__ __launch_bounds__(256)
void split_conv(const float* __restrict__ in, __nv_bfloat16* __restrict__ hi,
                __nv_bfloat16* __restrict__ lo, long n)
{
    long i = (long)blockIdx.x * blockDim.x + threadIdx.x;
    const long stride = (long)gridDim.x * blockDim.x;
    for (; i < n; i += stride) {
        float v = in[i];
        __nv_bfloat16 h = __float2bfloat16(v);
        hi[i] = h;
        lo[i] = __float2bfloat16(v - __bfloat162float(h));
    }
}

// ---------------------------------------------------------------------------
// fp32 [batch][R][C] -> transposed bf16 hi/lo [batch][C][R]
// ---------------------------------------------------------------------------
__global__ __launch_bounds__(256)
void split_conv_T(const float* __restrict__ in, __nv_bfloat16* __restrict__ hi,
                  __nv_bfloat16* __restrict__ lo, int R, int C)
{
    __shared__ float t[32][33];
    const long bo = (long)blockIdx.z * R * C;
    in += bo; hi += bo; lo += bo;
    const int rt = blockIdx.y * 32, ct = blockIdx.x * 32;
    #pragma unroll
    for (int j = 0; j < 4; j++)
        t[threadIdx.y + j * 8][threadIdx.x] =
            in[(long)(rt + threadIdx.y + j * 8) * C + ct + threadIdx.x];
    __syncthreads();
    #pragma unroll
    for (int j = 0; j < 4; j++) {
        float v = t[threadIdx.x][threadIdx.y + j * 8];
        long o = (long)(ct + threadIdx.y + j * 8) * R + rt + threadIdx.x;
        __nv_bfloat16 h = __float2bfloat16(v);
        hi[o] = h;
        lo[o] = __float2bfloat16(v - __bfloat162float(h));
    }
}

// ---------------------------------------------------------------------------
// Row softmax: read fp32 S, write bf16 hi/lo planes. One block per 2048-row.
// ---------------------------------------------------------------------------
__global__ __launch_bounds__(256)
void softmax_split(float* __restrict__ S, __nv_bfloat16* __restrict__ Sh,
                   __nv_bfloat16* __restrict__ Sl)
{
    const int cols = BB;
    float* row = S + (long)blockIdx.x * cols;
    __nv_bfloat16* rh = Sh + (long)blockIdx.x * cols;
    __nv_bfloat16* rl = Sl + (long)blockIdx.x * cols;
    const int tid = threadIdx.x;
    __shared__ float sred[8];

    float m = -1e30f;
    for (int i = tid; i < cols; i += 256) m = fmaxf(m, row[i]);
    #pragma unroll
    for (int o = 16; o; o >>= 1) m = fmaxf(m, __shfl_xor_sync(0xffffffffu, m, o));
    if ((tid & 31) == 0) sred[tid >> 5] = m;
    __syncthreads();
    if (tid == 0) {
        float t = sred[0];
        #pragma unroll
        for (int i = 1; i < 8; i++) t = fmaxf(t, sred[i]);
        sred[0] = t;
    }
    __syncthreads();
    m = sred[0];
    __syncthreads();

    float s = 0.f;
    for (int i = tid; i < cols; i += 256) {
        float e = __expf(row[i] - m);
        row[i] = e;
        s += e;
    }
    #pragma unroll
    for (int o = 16; o; o >>= 1) s += __shfl_xor_sync(0xffffffffu, s, o);
    if ((tid & 31) == 0) sred[tid >> 5] = s;
    __syncthreads();
    if (tid == 0) {
        float t = 0.f;
        #pragma unroll
        for (int i = 0; i < 8; i++) t += sred[i];
        sred[0] = t;
    }
    __syncthreads();
    const float inv = 1.f / sred[0];

    for (int i = tid; i < cols; i += 256) {
        float p = row[i] * inv;
        __nv_bfloat16 h = __float2bfloat16(p);
        rh[i] = h;
        rl[i] = __float2bfloat16(p - __bfloat162float(h));
    }
}

// ---------------------------------------------------------------------------
// Epilogue: head-concat reorder fused with out = concat @ Wo (32x32).
// ---------------------------------------------------------------------------
__global__ __launch_bounds__(256)
void out_proj(const float* __restrict__ AV, const float* __restrict__ Wo,
              float* __restrict__ out)
{
    __shared__ float Wos[32 * 32];
    const int tid = threadIdx.x;
    for (int i = tid; i < 1024; i += 256) Wos[i] = Wo[i];
    __syncthreads();

    const int warp = tid >> 5, lane = tid & 31;
    const int nwarps = (256 >> 5) * gridDim.x;
    const long nrows = (long)BB * NN;

    for (long r = (long)blockIdx.x * 8 + warp; r < nrows; r += nwarps) {
        const int b = (int)(r >> 7);
        const int n = (int)(r & 127);
        const int h = lane >> 2, j = lane & 3;
        const float c = AV[((long)h * BB + b) * UU + n * 4 + j];

        float acc = 0.f;
        #pragma unroll
        for (int d = 0; d < 32; d++) {
            float v = __shfl_sync(0xffffffffu, c, d);
            acc = fmaf(v, Wos[d * 32 + lane], acc);
        }
        out[r * DD + lane] = acc;
    }
}

// ---------------------------------------------------------------------------
// Launch
// ---------------------------------------------------------------------------
extern "C" void kernel_launch(void* const* d_in, const int* in_sizes, int n_in,
                              void* d_out, int out_size)
{
    const float* x  = (const float*)d_in[0];   // (2048,128,32) -> (2048,4096)
    const float* Wq = (const float*)d_in[1];   // (8,4096,512)
    const float* Wk = (const float*)d_in[2];
    const float* Wv = (const float*)d_in[3];
    const float* Wo = (const float*)d_in[4];   // (32,32)
    float* out = (float*)d_out;

    cudaFuncSetAttribute(gemm3x<0>, cudaFuncAttributeMaxDynamicSharedMemorySize, GEMM_SMEM);
    cudaFuncSetAttribute(gemm3x<1>, cudaFuncAttributeMaxDynamicSharedMemorySize, GEMM_SMEM);

    __nv_bfloat16 *Xh, *Xl, *Wqh, *Wql, *Wkh, *Wkl, *Wvh, *Wvl;
    __nv_bfloat16 *Qh, *Ql, *Kh, *Kl, *Vth, *Vtl, *Sh, *Sl;
    float *V, *S, *AV;
    cudaGetSymbolAddress((void**)&Xh,  g_Xh);  cudaGetSymbolAddress((void**)&Xl,  g_Xl);
    cudaGetSymbolAddress((void**)&Wqh, g_Wqh); cudaGetSymbolAddress((void**)&Wql, g_Wql);
    cudaGetSymbolAddress((void**)&Wkh, g_Wkh); cudaGetSymbolAddress((void**)&Wkl, g_Wkl);
    cudaGetSymbolAddress((void**)&Wvh, g_Wvh); cudaGetSymbolAddress((void**)&Wvl, g_Wvl);
    cudaGetSymbolAddress((void**)&V,   g_V);
    cudaGetSymbolAddress((void**)&Qh,  g_Qh);  cudaGetSymbolAddress((void**)&Ql,  g_Ql);
    cudaGetSymbolAddress((void**)&Kh,  g_Kh);  cudaGetSymbolAddress((void**)&Kl,  g_Kl);
    cudaGetSymbolAddress((void**)&Vth, g_Vth); cudaGetSymbolAddress((void**)&Vtl, g_Vtl);
    cudaGetSymbolAddress((void**)&S,   g_S);
    cudaGetSymbolAddress((void**)&Sh,  g_Sh);  cudaGetSymbolAddress((void**)&Sl,  g_Sl);
    cudaGetSymbolAddress((void**)&AV,  g_AV);

    const long sWt = (long)UU * NDD;     // per-head transposed-weight stride
    const long sQ  = (long)BB * UU;      // per-head Q/K/V/AV stride
    const long sVt = (long)UU * BB;      // per-head V^T stride
    const long sS  = (long)BB * BB;      // per-head scores stride

    dim3 blk(256);
    dim3 tblk(32, 8);

    // 0. split-convert inputs
    split_conv<<<4096, blk>>>(x, Xh, Xl, (long)BB * NDD);
    dim3 gWT(UU / 32, NDD / 32, HH);                    // (16,128,8)
    split_conv_T<<<gWT, tblk>>>(Wq, Wqh, Wql, NDD, UU);
    split_conv_T<<<gWT, tblk>>>(Wk, Wkh, Wkl, NDD, UU);
    split_conv_T<<<gWT, tblk>>>(Wv, Wvh, Wvl, NDD, UU);

    // 1-3. Projections (M=2048, N=512, K=4096). Q,K write split bf16 directly.
    dim3 gproj(UU / 128, BB / 128, HH);                 // (4,16,8)
    gemm3x<1><<<gproj, blk, GEMM_SMEM>>>(Xh, Xl, Wqh, Wql, nullptr, Qh, Ql,
                                         UU, NDD, 1.f, 0L, sWt, sQ);
    gemm3x<1><<<gproj, blk, GEMM_SMEM>>>(Xh, Xl, Wkh, Wkl, nullptr, Kh, Kl,
                                         UU, NDD, 1.f, 0L, sWt, sQ);
    gemm3x<0><<<gproj, blk, GEMM_SMEM>>>(Xh, Xl, Wvh, Wvl, V, nullptr, nullptr,
                                         UU, NDD, 1.f, 0L, sWt, sQ);

    // 4. transpose-split V
    dim3 gVT(UU / 32, BB / 32, HH);                     // (16,64,8)
    split_conv_T<<<gVT, tblk>>>(V, Vth, Vtl, BB, UU);

    // 5. S[h] = scale * Q[h] @ K[h]^T          (M=N=2048, K=512)
    dim3 gsc(BB / 128, BB / 128, HH);                   // (16,16,8)
    gemm3x<0><<<gsc, blk, GEMM_SMEM>>>(Qh, Ql, Kh, Kl, S, nullptr, nullptr,
                                       BB, UU, SCALE, sQ, sQ, sS);

    // 6. softmax rows -> bf16 hi/lo planes
    softmax_split<<<HH * BB, blk>>>(S, Sh, Sl);

    // 7. AV[h] = P[h] @ V[h]                   (M=2048, N=512, K=2048)
    dim3 gav(UU / 128, BB / 128, HH);                   // (4,16,8)
    gemm3x<0><<<gav, blk, GEMM_SMEM>>>(Sh, Sl, Vth, Vtl, AV, nullptr, nullptr,
                                       UU, BB, 1.f, sS, sVt, sQ);

    // 8. reorder + output projection
    out_proj<<<2048, blk>>>(AV, Wo, out);
}